// round 11
// baseline (speedup 1.0000x reference)
#include <cuda_runtime.h>
#include <cstdint>
#include <math.h>

typedef unsigned int u32;
typedef unsigned long long u64;

#define BB 128
#define HH 512
#define WW 512
#define HWL 262144
#define CAP 4096
#define NSEEDS 1000
#define NWORDS 16
#define WPB 8192           // words per batch plane (512*16)
#define HPAD 132           // padded row for per-thread byte counters

// ---------------- device scratch ----------------
__device__ u32 g_hist[BB][256];
__device__ u32 g_c255[BB][HWL / 4];        // packed bytes
__device__ u32 g_idxBG[BB][CAP];
__device__ u32 g_cntBG[BB];
__device__ u64 g_bufF[BB][CAP];
__device__ u32 g_cntF[BB];
__device__ u64 g_bufG[BB][CAP];
__device__ u32 g_cntG[BB];
__device__ int g_thi[BB], g_nbg[BB], g_cbin[BB], g_rbg[BB];
__device__ u32 g_thr23bg[BB];
__device__ u32 g_mf[BB];
__device__ uint2 g_kf[BB], g_kb[BB];
__device__ u32 g_bmH[BB][HH][NWORDS];      // H-eroded bits
__device__ u32 g_eligB[BB][HH][NWORDS];    // bg-eligible bits
__device__ u32 g_erodB[BB][HH][NWORDS];    // fully eroded bits
__device__ u32 g_mfg[BB][WPB];
__device__ u32 g_mbg[BB][WPB];

// ---------------- threefry-2x32 ----------------
__device__ __forceinline__ u32 rotl32(u32 x, int d) { return (x << d) | (x >> (32 - d)); }

__device__ __forceinline__ void tf2x32(u32 k0, u32 k1, u32 x0, u32 x1, u32& o0, u32& o1) {
    u32 ks0 = k0, ks1 = k1, ks2 = k0 ^ k1 ^ 0x1BD11BDAu;
    x0 += ks0; x1 += ks1;
    x0 += x1; x1 = rotl32(x1, 13); x1 ^= x0;
    x0 += x1; x1 = rotl32(x1, 15); x1 ^= x0;
    x0 += x1; x1 = rotl32(x1, 26); x1 ^= x0;
    x0 += x1; x1 = rotl32(x1,  6); x1 ^= x0;
    x0 += ks1; x1 += ks2 + 1u;
    x0 += x1; x1 = rotl32(x1, 17); x1 ^= x0;
    x0 += x1; x1 = rotl32(x1, 29); x1 ^= x0;
    x0 += x1; x1 = rotl32(x1, 16); x1 ^= x0;
    x0 += x1; x1 = rotl32(x1, 24); x1 ^= x0;
    x0 += ks2; x1 += ks0 + 2u;
    x0 += x1; x1 = rotl32(x1, 13); x1 ^= x0;
    x0 += x1; x1 = rotl32(x1, 15); x1 ^= x0;
    x0 += x1; x1 = rotl32(x1, 26); x1 ^= x0;
    x0 += x1; x1 = rotl32(x1,  6); x1 ^= x0;
    x0 += ks0; x1 += ks1 + 3u;
    x0 += x1; x1 = rotl32(x1, 17); x1 ^= x0;
    x0 += x1; x1 = rotl32(x1, 29); x1 ^= x0;
    x0 += x1; x1 = rotl32(x1, 16); x1 ^= x0;
    x0 += x1; x1 = rotl32(x1, 24); x1 ^= x0;
    x0 += ks1; x1 += ks2 + 4u;
    x0 += x1; x1 = rotl32(x1, 13); x1 ^= x0;
    x0 += x1; x1 = rotl32(x1, 15); x1 ^= x0;
    x0 += x1; x1 = rotl32(x1, 26); x1 ^= x0;
    x0 += x1; x1 = rotl32(x1,  6); x1 ^= x0;
    x0 += ks2; x1 += ks0 + 5u;
    o0 = x0; o1 = x1;
}

// ---------------- K1: zero scratch + per-batch keys (fused) ----------------
__global__ void k_init() {
    int t = blockIdx.x * blockDim.x + threadIdx.x;
    int stride = gridDim.x * blockDim.x;
    for (int i = t; i < BB * WPB; i += stride) { (&g_mfg[0][0])[i] = 0; (&g_mbg[0][0])[i] = 0; }
    for (int i = t; i < BB * 256; i += stride) (&g_hist[0][0])[i] = 0;
    if (t < BB) {
        g_cntBG[t] = 0; g_cntF[t] = 0; g_cntG[t] = 0; g_mf[t] = 0;
        int b = t;
        u32 a0, a1;
        tf2x32(0u, 42u, 0u, (u32)b, a0, a1);
        u32 kf0, kf1, kb0, kb1, kz0, kz1;
        tf2x32(a0, a1, 0u, 0u, kf0, kf1);
        tf2x32(a0, a1, 0u, 1u, kb0, kb1);
        tf2x32(a0, a1, 0u, 2u, kz0, kz1);
        g_kf[b] = make_uint2(kf0, kf1);
        g_kb[b] = make_uint2(kb0, kb1);
        u32 z0, z1;
        tf2x32(kz0, kz1, 0u, 0u, z0, z1);
        u32 zb = z0 ^ z1;
        float f = __fsub_rn(__uint_as_float((zb >> 9) | 0x3f800000u), 1.0f);
        float z = fmaxf(0.3f, __fadd_rn(__fmul_rn(f, __fsub_rn(0.7f, 0.3f)), 0.3f));
        int nbg = (int)ceilf(__fmul_rn(z, 262144.0f));
        g_nbg[b] = nbg;
        g_thr23bg[b] = (u32)(8388608.0 * (1.0 - 1500.0 / (double)nbg));
    }
}

// ---------------- K2: histogram via per-thread byte counters (no atomics) ----------------
__global__ void k_histc(const float4* __restrict__ x4) {
    __shared__ unsigned char sh8[256 * HPAD];   // 33792 B
    int b = blockIdx.y, t = threadIdx.x;        // 128 threads
    u32* shw = (u32*)sh8;
    for (int i = t; i < 256 * HPAD / 4; i += 128) shw[i] = 0;
    __syncthreads();
    size_t base4 = (size_t)b * (HWL / 4);
    int start = blockIdx.x * 2048;              // 32 blocks/batch, 2048 float4 each
#pragma unroll 4
    for (int k = 0; k < 16; k++) {
        int i4 = start + k * 128 + t;
        float4 v = x4[base4 + i4];
        int b0 = (int)floorf(__fmul_rn(v.x, 255.0f)); if (b0 < 0) b0 = 0; if (b0 > 255) b0 = 255;
        int b1 = (int)floorf(__fmul_rn(v.y, 255.0f)); if (b1 < 0) b1 = 0; if (b1 > 255) b1 = 255;
        int b2 = (int)floorf(__fmul_rn(v.z, 255.0f)); if (b2 < 0) b2 = 0; if (b2 > 255) b2 = 255;
        int b3 = (int)floorf(__fmul_rn(v.w, 255.0f)); if (b3 < 0) b3 = 0; if (b3 > 255) b3 = 255;
        sh8[b0 * HPAD + t]++;
        sh8[b1 * HPAD + t]++;
        sh8[b2 * HPAD + t]++;
        sh8[b3 * HPAD + t]++;
        g_c255[b][i4] = (u32)b0 | ((u32)b1 << 8) | ((u32)b2 << 16) | ((u32)b3 << 24);
    }
    __syncthreads();
#pragma unroll
    for (int h = 0; h < 2; h++) {
        int bin = t + h * 128;
        const u32* rowp = (const u32*)&sh8[bin * HPAD];
        u32 acc = 0;
#pragma unroll
        for (int j = 0; j < 32; j++) acc = __dp4a(rowp[j], 0x01010101u, acc);
        if (acc) atomicAdd(&g_hist[b][bin], acc);
    }
}

// ---------------- K3: Otsu (serial-exact cumsum, parallel sigma/argmax) + bg cutoff ----------------
__global__ void k_scan1() {
    __shared__ u32 s256[256];
    __shared__ float cw[256], cm[256];
    __shared__ u64 red[256];
    int b = blockIdx.x, t = threadIdx.x;
    s256[t] = g_hist[b][t];
    __syncthreads();
    if (t == 0) {
        float w = 0.0f, m = 0.0f;
        for (int q = 0; q < 256; q++) {
            w = __fadd_rn(w, (float)s256[q]);
            m = __fadd_rn(m, __fmul_rn((float)s256[q], (float)q));
            cw[q] = w; cm[q] = m;
        }
    }
    __syncthreads();
    const float total = 262144.0f;
    float mT = cm[255];
    float w = cw[t], m = cm[t];
    float denom = __fmul_rn(w, __fsub_rn(total, w));
    float sig = 0.0f;
    if (denom > 0.0f) {
        float num = __fsub_rn(__fmul_rn(mT, w), __fmul_rn(total, m));
        sig = __fdiv_rn(__fmul_rn(num, num),
                        __fmul_rn(__fmul_rn(denom, total), total));
    }
    red[t] = (((u64)__float_as_uint(sig)) << 32) | (u32)(255 - t);
    __syncthreads();
    for (int s = 128; s > 0; s >>= 1) {
        if (t < s) { u64 o = red[t + s]; if (o > red[t]) red[t] = o; }
        __syncthreads();
    }
    if (t == 0) {
        int arg = 255 - (int)(red[0] & 0xFFFFFFFFu);
        if (arg == 0) arg = 1;
        if (arg == 255) arg = 254;
        g_thi[b] = arg;
    }
    u32 n = (u32)g_nbg[b];
    u32 cwt = (u32)cw[t];
    u32 cwp = (t > 0) ? (u32)cw[t - 1] : 0u;
    if (cwt >= n && cwp < n) {
        g_cbin[b] = t;
        g_rbg[b] = (int)(n - cwp);
    }
}

// ---------------- K4: horizontal erosion, SIMD bytes, 1 thread = 32 pixels ----------------
__global__ void k_erodeH() {
    __shared__ u32 sbit[16][NWORDS];
    int b = blockIdx.y;
    int rowBase = blockIdx.x * 16;
    int t = threadIdx.x;            // 0..255
    int lr = t >> 4, w = t & 15;
    int row = rowBase + lr;
    const u32* src = &g_c255[b][0] + row * 128 + w * 8;
    int thi = g_thi[b], cbin = g_cbin[b];
    u32 thiB = 0x01010101u * (u32)thi;
    u32 cbinB = 0x01010101u * (u32)cbin;
    u32 bits = 0, ebits = 0;
#pragma unroll
    for (int k = 0; k < 8; k++) {
        u32 v = src[k];
        u32 gt = __vcmpgtu4(v, thiB);
        u32 lt = __vcmpltu4(v, cbinB);
        u32 eq = __vcmpeq4(v, cbinB);
        bits  |= (((gt >> 7) & 1u) | ((gt >> 14) & 2u) | ((gt >> 21) & 4u) | ((gt >> 28) & 8u)) << (k * 4);
        ebits |= (((lt >> 7) & 1u) | ((lt >> 14) & 2u) | ((lt >> 21) & 4u) | ((lt >> 28) & 8u)) << (k * 4);
        if (eq) {
#pragma unroll
            for (int q = 0; q < 4; q++)
                if ((eq >> (8 * q + 7)) & 1u) {
                    u32 pos = atomicAdd(&g_cntBG[b], 1u);
                    if (pos < CAP) g_idxBG[b][pos] = (u32)(row * WW + w * 32 + k * 4 + q);
                }
        }
    }
    g_eligB[b][row][w] = ebits;
    sbit[lr][w] = bits;
    __syncthreads();
    u32 mid = ~sbit[lr][w];
    u32 lo = (w > 0) ? ~sbit[lr][w - 1] : 0u;
    u32 hi = (w < NWORDS - 1) ? ~sbit[lr][w + 1] : 0u;
    u32 d = mid;
#pragma unroll
    for (int s2 = 1; s2 <= 5; s2++) {
        d |= (mid << s2) | (lo >> (32 - s2));
        d |= (mid >> s2) | (hi << (32 - s2));
    }
    g_bmH[b][row][w] = ~d;
}

// ---------------- K5 (fused): vertical erosion  ||  exact cutoff-bin rank resolve ----------------
__global__ void k_eVs(const float* __restrict__ x) {
    if (blockIdx.x < 512) {
        // vertical erosion + fg count
        int t = blockIdx.x * 256 + threadIdx.x;
        int b = t >> 10;
        int rem = t & 1023;
        int w = rem & 15;
        int chunk = rem >> 4;
        int r0 = chunk * 8;
        u32 win[18];
#pragma unroll
        for (int k = 0; k < 18; k++) {
            int r = r0 - 5 + k;
            win[k] = (r < 0 || r >= HH) ? 0xFFFFFFFFu : g_bmH[b][r][w];
        }
        int pc = 0;
#pragma unroll
        for (int k = 0; k < 8; k++) {
            u32 v = 0xFFFFFFFFu;
#pragma unroll
            for (int s = 0; s < 11; s++) v &= win[k + s];
            g_erodB[b][r0 + k][w] = v;
            pc += __popc(v);
        }
        if (pc) atomicAdd(&g_mf[b], (u32)pc);
    } else {
        // selBG: resolve cutoff bin exactly -> OR eligibility bits
        __shared__ u64 s[CAP];
        int b = blockIdx.x - 512;
        int n = (int)min(g_cntBG[b], (u32)CAP);
        int r = g_rbg[b];
        size_t base = (size_t)b * HWL;
        for (int i = threadIdx.x; i < n; i += blockDim.x) {
            u32 idx = g_idxBG[b][i];
            float c = x[base + idx];
            s[i] = (((u64)__float_as_uint(c)) << 18) | idx;
        }
        __syncthreads();
        for (int i = threadIdx.x; i < n; i += blockDim.x) {
            u64 e = s[i];
            int less = 0;
            for (int j2 = 0; j2 < n; j2++) less += (s[j2] < e);
            if (less < r) {
                u32 idx = (u32)(e & 0x3FFFFu);
                atomicOr(&g_eligB[b][idx >> 9][(idx & 511) >> 5], 1u << (idx & 31));
            }
        }
    }
}

// ---------------- K6 (fused): bg + fg score selection ----------------
__global__ void k_sel() {
    int b = blockIdx.y;
    int bx = blockIdx.x;
    if (bx < 32) {
        // bg threefry over eligible bits
        int wi = bx * 256 + threadIdx.x;
        int row = wi >> 4, w = wi & 15;
        u32 bits = g_eligB[b][row][w];
        if (!bits) return;
        u32 thr = g_thr23bg[b];
        uint2 kb = g_kb[b];
        int pbase = row * WW + w * 32;
        while (bits) {
            int l = __ffs(bits) - 1;
            bits &= bits - 1;
            u32 idx = (u32)(pbase + l);
            u32 o0, o1;
            tf2x32(kb.x, kb.y, 0u, idx, o0, o1);
            u32 s23 = (o0 ^ o1) >> 9;
            if (s23 >= thr) {
                u32 pos = atomicAdd(&g_cntG[b], 1u);
                if (pos < CAP) g_bufG[b][pos] = (((u64)s23) << 18) | (u32)(0x3FFFFu - idx);
            }
        }
    } else {
        // fg selection (fast path: all eroded are seeds)
        u32 mf = g_mf[b];
        uint2 kf = g_kf[b];
        u32 thrf = 0;
        if (mf > 3000u) thrf = (u32)(8388608.0 * (1.0 - 1500.0 / (double)mf));
        for (int wi = (bx - 32) * 256 + threadIdx.x; wi < WPB; wi += 8 * 256) {
            int row = wi >> 4, w = wi & 15;
            u32 bits = g_erodB[b][row][w];
            if (mf <= NSEEDS) { g_mfg[b][wi] = bits; continue; }
            int pbase = row * WW + w * 32;
            while (bits) {
                int l = __ffs(bits) - 1;
                bits &= bits - 1;
                u32 idx = (u32)(pbase + l);
                u32 o0, o1;
                tf2x32(kf.x, kf.y, 0u, idx, o0, o1);
                u32 s23 = (o0 ^ o1) >> 9;
                if (s23 >= thrf) {
                    u32 pos = atomicAdd(&g_cntF[b], 1u);
                    if (pos < CAP) g_bufF[b][pos] = (((u64)s23) << 18) | (u32)(0x3FFFFu - idx);
                }
            }
        }
    }
}

// ---------------- K7: exact top-1000 among candidates -> seed bitmasks ----------------
__global__ void k_finish() {
    __shared__ u64 s[CAP];
    int bi = blockIdx.x;
    int b = bi >> 1, which = bi & 1;
    int n;
    const u64* buf;
    u32* plane;
    if (which == 0) {
        n = (int)min(g_cntG[b], (u32)CAP); buf = g_bufG[b]; plane = g_mbg[b];
    } else {
        if (g_mf[b] <= NSEEDS) return;
        n = (int)min(g_cntF[b], (u32)CAP); buf = g_bufF[b]; plane = g_mfg[b];
    }
    for (int i = threadIdx.x; i < n; i += blockDim.x) s[i] = buf[i];
    __syncthreads();
    for (int i = threadIdx.x; i < n; i += blockDim.x) {
        u64 e = s[i];
        int g = 0;
        for (int j2 = 0; j2 < n; j2++) g += (s[j2] > e);
        if (g < NSEEDS) {
            u32 idx = 0x3FFFFu - (u32)(e & 0x3FFFFu);
            atomicOr(&plane[idx >> 5], 1u << (idx & 31));
        }
    }
}

// ---------------- K8: word-level 3x3 dilation + overlap removal + labels ----------------
__global__ void k_out(float* __restrict__ out) {
    int b = blockIdx.y;
    int t = blockIdx.x * blockDim.x + threadIdx.x;
    int row = t >> 4, w = t & 15;
    u32 F = 0, Bg = 0;
#pragma unroll
    for (int dr = -1; dr <= 1; dr++) {
        int r = row + dr;
        if (r < 0 || r >= HH) continue;
        int baseW = r * NWORDS;
        u32 fm = g_mfg[b][baseW + w];
        u32 fl = (w > 0) ? g_mfg[b][baseW + w - 1] : 0u;
        u32 fh = (w < NWORDS - 1) ? g_mfg[b][baseW + w + 1] : 0u;
        u32 bm = g_mbg[b][baseW + w];
        u32 bl = (w > 0) ? g_mbg[b][baseW + w - 1] : 0u;
        u32 bh = (w < NWORDS - 1) ? g_mbg[b][baseW + w + 1] : 0u;
        F  |= fm | (fm << 1) | (fl >> 31) | (fm >> 1) | (fh << 31);
        Bg |= bm | (bm << 1) | (bl >> 31) | (bm >> 1) | (bh << 31);
    }
    size_t ob = (size_t)b * HWL + (size_t)row * WW + w * 32;
#pragma unroll
    for (int k = 0; k < 32; k += 4) {
        float4 v;
        float* pv = (float*)&v;
#pragma unroll
        for (int q = 0; q < 4; q++) {
            int bit = k + q;
            int fg = (F >> bit) & 1, bg = (Bg >> bit) & 1;
            pv[q] = fg ? (bg ? -255.0f : 1.0f) : (bg ? 0.0f : -255.0f);
        }
        *(float4*)(out + ob + k) = v;
    }
}

// ---------------- launch ----------------
extern "C" void kernel_launch(void* const* d_in, const int* in_sizes, int n_in,
                              void* d_out, int out_size) {
    const float* x = (const float*)d_in[0];
    float* out = (float*)d_out;
    (void)in_sizes; (void)n_in; (void)out_size;

    k_init<<<2048, 256>>>();
    k_histc<<<dim3(32, BB), 128>>>((const float4*)x);
    k_scan1<<<BB, 256>>>();
    k_erodeH<<<dim3(32, BB), 256>>>();
    k_eVs<<<512 + BB, 256>>>(x);
    k_sel<<<dim3(40, BB), 256>>>();
    k_finish<<<2 * BB, 512>>>();
    k_out<<<dim3(32, BB), 256>>>(out);
}

// round 14
// speedup vs baseline: 1.1715x; 1.1715x over previous
#include <cuda_runtime.h>
#include <cstdint>
#include <math.h>

typedef unsigned int u32;
typedef unsigned long long u64;

#define BB 128
#define HH 512
#define WW 512
#define HWL 262144
#define CAP 4096
#define NSEEDS 1000
#define NWORDS 16
#define WPB 8192           // words per batch plane (512*16)
#define HPAD 132           // padded row for per-thread byte counters

// ---------------- device scratch ----------------
__device__ u32 g_hist[BB][256];
__device__ u32 g_c255[BB][HWL / 4];        // packed bytes
__device__ u32 g_idxBG[BB][CAP];
__device__ u32 g_cntBG[BB];
__device__ u64 g_bufF[BB][CAP];
__device__ u32 g_cntF[BB];
__device__ u64 g_bufG[BB][CAP];
__device__ u32 g_cntG[BB];
__device__ int g_thi[BB], g_nbg[BB], g_cbin[BB], g_rbg[BB];
__device__ u32 g_thr23bg[BB];
__device__ u32 g_mf[BB];
__device__ uint2 g_kf[BB], g_kb[BB];
__device__ u32 g_bmH[BB][HH][NWORDS];      // H-eroded bits
__device__ u32 g_eligB[BB][HH][NWORDS];    // bg-eligible bits
__device__ u32 g_erodB[BB][HH][NWORDS];    // fully eroded bits
__device__ u32 g_mfg[BB][WPB];
__device__ u32 g_mbg[BB][WPB];

// ---------------- threefry-2x32 ----------------
__device__ __forceinline__ u32 rotl32(u32 x, int d) { return (x << d) | (x >> (32 - d)); }

__device__ __forceinline__ void tf2x32(u32 k0, u32 k1, u32 x0, u32 x1, u32& o0, u32& o1) {
    u32 ks0 = k0, ks1 = k1, ks2 = k0 ^ k1 ^ 0x1BD11BDAu;
    x0 += ks0; x1 += ks1;
    x0 += x1; x1 = rotl32(x1, 13); x1 ^= x0;
    x0 += x1; x1 = rotl32(x1, 15); x1 ^= x0;
    x0 += x1; x1 = rotl32(x1, 26); x1 ^= x0;
    x0 += x1; x1 = rotl32(x1,  6); x1 ^= x0;
    x0 += ks1; x1 += ks2 + 1u;
    x0 += x1; x1 = rotl32(x1, 17); x1 ^= x0;
    x0 += x1; x1 = rotl32(x1, 29); x1 ^= x0;
    x0 += x1; x1 = rotl32(x1, 16); x1 ^= x0;
    x0 += x1; x1 = rotl32(x1, 24); x1 ^= x0;
    x0 += ks2; x1 += ks0 + 2u;
    x0 += x1; x1 = rotl32(x1, 13); x1 ^= x0;
    x0 += x1; x1 = rotl32(x1, 15); x1 ^= x0;
    x0 += x1; x1 = rotl32(x1, 26); x1 ^= x0;
    x0 += x1; x1 = rotl32(x1,  6); x1 ^= x0;
    x0 += ks0; x1 += ks1 + 3u;
    x0 += x1; x1 = rotl32(x1, 17); x1 ^= x0;
    x0 += x1; x1 = rotl32(x1, 29); x1 ^= x0;
    x0 += x1; x1 = rotl32(x1, 16); x1 ^= x0;
    x0 += x1; x1 = rotl32(x1, 24); x1 ^= x0;
    x0 += ks1; x1 += ks2 + 4u;
    x0 += x1; x1 = rotl32(x1, 13); x1 ^= x0;
    x0 += x1; x1 = rotl32(x1, 15); x1 ^= x0;
    x0 += x1; x1 = rotl32(x1, 26); x1 ^= x0;
    x0 += x1; x1 = rotl32(x1,  6); x1 ^= x0;
    x0 += ks2; x1 += ks0 + 5u;
    o0 = x0; o1 = x1;
}

// ---------------- K1: zero scratch + per-batch keys (fused) ----------------
__global__ void k_init() {
    int t = blockIdx.x * blockDim.x + threadIdx.x;
    int stride = gridDim.x * blockDim.x;
    for (int i = t; i < BB * WPB; i += stride) { (&g_mfg[0][0])[i] = 0; (&g_mbg[0][0])[i] = 0; }
    for (int i = t; i < BB * 256; i += stride) (&g_hist[0][0])[i] = 0;
    if (t < BB) {
        g_cntBG[t] = 0; g_cntF[t] = 0; g_cntG[t] = 0; g_mf[t] = 0;
        int b = t;
        u32 a0, a1;
        tf2x32(0u, 42u, 0u, (u32)b, a0, a1);
        u32 kf0, kf1, kb0, kb1, kz0, kz1;
        tf2x32(a0, a1, 0u, 0u, kf0, kf1);
        tf2x32(a0, a1, 0u, 1u, kb0, kb1);
        tf2x32(a0, a1, 0u, 2u, kz0, kz1);
        g_kf[b] = make_uint2(kf0, kf1);
        g_kb[b] = make_uint2(kb0, kb1);
        u32 z0, z1;
        tf2x32(kz0, kz1, 0u, 0u, z0, z1);
        u32 zb = z0 ^ z1;
        float f = __fsub_rn(__uint_as_float((zb >> 9) | 0x3f800000u), 1.0f);
        float z = fmaxf(0.3f, __fadd_rn(__fmul_rn(f, __fsub_rn(0.7f, 0.3f)), 0.3f));
        int nbg = (int)ceilf(__fmul_rn(z, 262144.0f));
        g_nbg[b] = nbg;
        g_thr23bg[b] = (u32)(8388608.0 * (1.0 - 1500.0 / (double)nbg));
    }
}

// ---------------- K2: histogram via per-thread byte counters (no atomics) ----------------
__global__ void k_histc(const float4* __restrict__ x4) {
    __shared__ unsigned char sh8[256 * HPAD];   // 33792 B
    int b = blockIdx.y, t = threadIdx.x;        // 128 threads
    u32* shw = (u32*)sh8;
    for (int i = t; i < 256 * HPAD / 4; i += 128) shw[i] = 0;
    __syncthreads();
    size_t base4 = (size_t)b * (HWL / 4);
    int start = blockIdx.x * 2048;              // 32 blocks/batch
#pragma unroll 4
    for (int k = 0; k < 16; k++) {
        int i4 = start + k * 128 + t;
        float4 v = x4[base4 + i4];
        int b0 = (int)floorf(__fmul_rn(v.x, 255.0f)); if (b0 < 0) b0 = 0; if (b0 > 255) b0 = 255;
        int b1 = (int)floorf(__fmul_rn(v.y, 255.0f)); if (b1 < 0) b1 = 0; if (b1 > 255) b1 = 255;
        int b2 = (int)floorf(__fmul_rn(v.z, 255.0f)); if (b2 < 0) b2 = 0; if (b2 > 255) b2 = 255;
        int b3 = (int)floorf(__fmul_rn(v.w, 255.0f)); if (b3 < 0) b3 = 0; if (b3 > 255) b3 = 255;
        sh8[b0 * HPAD + t]++;
        sh8[b1 * HPAD + t]++;
        sh8[b2 * HPAD + t]++;
        sh8[b3 * HPAD + t]++;
        g_c255[b][i4] = (u32)b0 | ((u32)b1 << 8) | ((u32)b2 << 16) | ((u32)b3 << 24);
    }
    __syncthreads();
#pragma unroll
    for (int h = 0; h < 2; h++) {
        int bin = t + h * 128;
        const u32* rowp = (const u32*)&sh8[bin * HPAD];
        u32 acc = 0;
#pragma unroll
        for (int j = 0; j < 32; j++) acc = __dp4a(rowp[j], 0x01010101u, acc);
        if (acc) atomicAdd(&g_hist[b][bin], acc);
    }
}

// ---------------- K3: Otsu (serial-exact cumsum, parallel sigma/argmax) + bg cutoff ----------------
__global__ void k_scan1() {
    __shared__ u32 s256[256];
    __shared__ float cw[256], cm[256];
    __shared__ u64 red[256];
    int b = blockIdx.x, t = threadIdx.x;
    s256[t] = g_hist[b][t];
    __syncthreads();
    if (t == 0) {
        float w = 0.0f, m = 0.0f;
        for (int q = 0; q < 256; q++) {
            w = __fadd_rn(w, (float)s256[q]);
            m = __fadd_rn(m, __fmul_rn((float)s256[q], (float)q));
            cw[q] = w; cm[q] = m;
        }
    }
    __syncthreads();
    const float total = 262144.0f;
    float mT = cm[255];
    float w = cw[t], m = cm[t];
    float denom = __fmul_rn(w, __fsub_rn(total, w));
    float sig = 0.0f;
    if (denom > 0.0f) {
        float num = __fsub_rn(__fmul_rn(mT, w), __fmul_rn(total, m));
        sig = __fdiv_rn(__fmul_rn(num, num),
                        __fmul_rn(__fmul_rn(denom, total), total));
    }
    red[t] = (((u64)__float_as_uint(sig)) << 32) | (u32)(255 - t);
    __syncthreads();
    for (int s = 128; s > 0; s >>= 1) {
        if (t < s) { u64 o = red[t + s]; if (o > red[t]) red[t] = o; }
        __syncthreads();
    }
    if (t == 0) {
        int arg = 255 - (int)(red[0] & 0xFFFFFFFFu);
        if (arg == 0) arg = 1;
        if (arg == 255) arg = 254;
        g_thi[b] = arg;
    }
    u32 n = (u32)g_nbg[b];
    u32 cwt = (u32)cw[t];
    u32 cwp = (t > 0) ? (u32)cw[t - 1] : 0u;
    if (cwt >= n && cwp < n) {
        g_cbin[b] = t;
        g_rbg[b] = (int)(n - cwp);
    }
}

// ---------------- K4: horizontal erosion — wide loads + multiply bit-pack ----------------
__global__ void k_erodeH() {
    __shared__ u32 sbit[16][NWORDS];
    int b = blockIdx.y;
    int rowBase = blockIdx.x * 16;
    int t = threadIdx.x;            // 0..255
    int lr = t >> 4, w = t & 15;
    int row = rowBase + lr;
    const uint4* src = (const uint4*)(&g_c255[b][0] + row * 128 + w * 8);
    uint4 v0 = src[0];
    uint4 v1 = src[1];
    int thi = g_thi[b], cbin = g_cbin[b];
    u32 thiB = 0x01010101u * (u32)thi;
    u32 cbinB = 0x01010101u * (u32)cbin;
    u32 vv[8] = {v0.x, v0.y, v0.z, v0.w, v1.x, v1.y, v1.z, v1.w};
    u32 bits = 0, ebits = 0, qbits = 0;
#pragma unroll
    for (int k = 0; k < 8; k++) {
        u32 v = vv[k];
        u32 gt = (__vcmpgtu4(v, thiB) >> 7) & 0x01010101u;
        u32 lt = (__vcmpltu4(v, cbinB) >> 7) & 0x01010101u;
        u32 eq = (__vcmpeq4(v, cbinB) >> 7) & 0x01010101u;
        bits  |= (((gt * 0x01020408u) >> 24) & 0xFu) << (k * 4);
        ebits |= (((lt * 0x01020408u) >> 24) & 0xFu) << (k * 4);
        qbits |= (((eq * 0x01020408u) >> 24) & 0xFu) << (k * 4);
    }
    g_eligB[b][row][w] = ebits;
    while (qbits) {
        int l = __ffs(qbits) - 1;
        qbits &= qbits - 1;
        u32 pos = atomicAdd(&g_cntBG[b], 1u);
        if (pos < CAP) g_idxBG[b][pos] = (u32)(row * WW + w * 32 + l);
    }
    sbit[lr][w] = bits;
    __syncthreads();
    u32 mid = ~sbit[lr][w];
    u32 lo = (w > 0) ? ~sbit[lr][w - 1] : 0u;
    u32 hi = (w < NWORDS - 1) ? ~sbit[lr][w + 1] : 0u;
    u32 d = mid;
#pragma unroll
    for (int s2 = 1; s2 <= 5; s2++) {
        d |= (mid << s2) | (lo >> (32 - s2));
        d |= (mid >> s2) | (hi << (32 - s2));
    }
    g_bmH[b][row][w] = ~d;
}

// ---------------- K5: vertical erosion + fg count ----------------
__global__ void k_erodeV() {
    int t = blockIdx.x * blockDim.x + threadIdx.x;
    if (t >= BB * NWORDS * 64) return;
    int b = t >> 10;
    int rem = t & 1023;
    int w = rem & 15;
    int chunk = rem >> 4;
    int r0 = chunk * 8;
    u32 win[18];
#pragma unroll
    for (int k = 0; k < 18; k++) {
        int r = r0 - 5 + k;
        win[k] = (r < 0 || r >= HH) ? 0xFFFFFFFFu : g_bmH[b][r][w];
    }
    int pc = 0;
#pragma unroll
    for (int k = 0; k < 8; k++) {
        u32 v = 0xFFFFFFFFu;
#pragma unroll
        for (int s = 0; s < 11; s++) v &= win[k + s];
        g_erodB[b][r0 + k][w] = v;
        pc += __popc(v);
    }
    if (pc) atomicAdd(&g_mf[b], (u32)pc);
}

// ---------------- K6: resolve cutoff bin exactly -> OR eligibility bits ----------------
__global__ void k_selBG(const float* __restrict__ x) {
    __shared__ u64 s[CAP];
    int b = blockIdx.x;
    int n = (int)min(g_cntBG[b], (u32)CAP);
    int r = g_rbg[b];
    size_t base = (size_t)b * HWL;
    for (int i = threadIdx.x; i < n; i += blockDim.x) {
        u32 idx = g_idxBG[b][i];
        float c = x[base + idx];
        s[i] = (((u64)__float_as_uint(c)) << 18) | idx;
    }
    __syncthreads();
    for (int i = threadIdx.x; i < n; i += blockDim.x) {
        u64 e = s[i];
        int less = 0;
        for (int j2 = 0; j2 < n; j2++) less += (s[j2] < e);
        if (less < r) {
            u32 idx = (u32)(e & 0x3FFFFu);
            atomicOr(&g_eligB[b][idx >> 9][(idx & 511) >> 5], 1u << (idx & 31));
        }
    }
}

// ---------------- K7: bg threefry over eligible bits only -> candidates ----------------
__global__ void k_bgsel() {
    int b = blockIdx.y;
    int wi = blockIdx.x * blockDim.x + threadIdx.x;
    int row = wi >> 4, w = wi & 15;
    u32 bits = g_eligB[b][row][w];
    if (!bits) return;
    u32 thr = g_thr23bg[b];
    uint2 kb = g_kb[b];
    int pbase = row * WW + w * 32;
    while (bits) {
        int l = __ffs(bits) - 1;
        bits &= bits - 1;
        u32 idx = (u32)(pbase + l);
        u32 o0, o1;
        tf2x32(kb.x, kb.y, 0u, idx, o0, o1);
        u32 s23 = (o0 ^ o1) >> 9;
        if (s23 >= thr) {
            u32 pos = atomicAdd(&g_cntG[b], 1u);
            if (pos < CAP) g_bufG[b][pos] = (((u64)s23) << 18) | (u32)(0x3FFFFu - idx);
        }
    }
}

// ---------------- K8: fg selection (fast path: all eroded are seeds) ----------------
__global__ void k_fgsel() {
    int b = blockIdx.y;
    u32 mf = g_mf[b];
    uint2 kf = g_kf[b];
    u32 thrf = 0;
    if (mf > 3000u) thrf = (u32)(8388608.0 * (1.0 - 1500.0 / (double)mf));
    int stride = gridDim.x * blockDim.x;
    for (int wi = blockIdx.x * blockDim.x + threadIdx.x; wi < WPB; wi += stride) {
        int row = wi >> 4, w = wi & 15;
        u32 bits = g_erodB[b][row][w];
        if (mf <= NSEEDS) { g_mfg[b][wi] = bits; continue; }
        int pbase = row * WW + w * 32;
        while (bits) {
            int l = __ffs(bits) - 1;
            bits &= bits - 1;
            u32 idx = (u32)(pbase + l);
            u32 o0, o1;
            tf2x32(kf.x, kf.y, 0u, idx, o0, o1);
            u32 s23 = (o0 ^ o1) >> 9;
            if (s23 >= thrf) {
                u32 pos = atomicAdd(&g_cntF[b], 1u);
                if (pos < CAP) g_bufF[b][pos] = (((u64)s23) << 18) | (u32)(0x3FFFFu - idx);
            }
        }
    }
}

// ---------------- K9: exact top-1000 among candidates -> seed bitmasks ----------------
__global__ void k_finish() {
    __shared__ u64 s[CAP];
    int bi = blockIdx.x;
    int b = bi >> 1, which = bi & 1;
    int n;
    const u64* buf;
    u32* plane;
    if (which == 0) {
        n = (int)min(g_cntG[b], (u32)CAP); buf = g_bufG[b]; plane = g_mbg[b];
    } else {
        if (g_mf[b] <= NSEEDS) return;
        n = (int)min(g_cntF[b], (u32)CAP); buf = g_bufF[b]; plane = g_mfg[b];
    }
    for (int i = threadIdx.x; i < n; i += blockDim.x) s[i] = buf[i];
    __syncthreads();
    for (int i = threadIdx.x; i < n; i += blockDim.x) {
        u64 e = s[i];
        int g = 0;
        for (int j2 = 0; j2 < n; j2++) g += (s[j2] > e);
        if (g < NSEEDS) {
            u32 idx = 0x3FFFFu - (u32)(e & 0x3FFFFu);
            atomicOr(&plane[idx >> 5], 1u << (idx & 31));
        }
    }
}

// ---------------- K10: word-level 3x3 dilation + overlap removal + labels ----------------
__global__ void k_out(float* __restrict__ out) {
    int b = blockIdx.y;
    int t = blockIdx.x * blockDim.x + threadIdx.x;
    int row = t >> 4, w = t & 15;
    u32 F = 0, Bg = 0;
#pragma unroll
    for (int dr = -1; dr <= 1; dr++) {
        int r = row + dr;
        if (r < 0 || r >= HH) continue;
        int baseW = r * NWORDS;
        u32 fm = g_mfg[b][baseW + w];
        u32 fl = (w > 0) ? g_mfg[b][baseW + w - 1] : 0u;
        u32 fh = (w < NWORDS - 1) ? g_mfg[b][baseW + w + 1] : 0u;
        u32 bm = g_mbg[b][baseW + w];
        u32 bl = (w > 0) ? g_mbg[b][baseW + w - 1] : 0u;
        u32 bh = (w < NWORDS - 1) ? g_mbg[b][baseW + w + 1] : 0u;
        F  |= fm | (fm << 1) | (fl >> 31) | (fm >> 1) | (fh << 31);
        Bg |= bm | (bm << 1) | (bl >> 31) | (bm >> 1) | (bh << 31);
    }
    size_t ob = (size_t)b * HWL + (size_t)row * WW + w * 32;
#pragma unroll
    for (int k = 0; k < 32; k += 4) {
        float4 v;
        float* pv = (float*)&v;
#pragma unroll
        for (int q = 0; q < 4; q++) {
            int bit = k + q;
            int fg = (F >> bit) & 1, bg = (Bg >> bit) & 1;
            pv[q] = fg ? (bg ? -255.0f : 1.0f) : (bg ? 0.0f : -255.0f);
        }
        *(float4*)(out + ob + k) = v;
    }
}

// ---------------- launch ----------------
extern "C" void kernel_launch(void* const* d_in, const int* in_sizes, int n_in,
                              void* d_out, int out_size) {
    const float* x = (const float*)d_in[0];
    float* out = (float*)d_out;
    (void)in_sizes; (void)n_in; (void)out_size;

    k_init<<<2048, 256>>>();
    k_histc<<<dim3(32, BB), 128>>>((const float4*)x);
    k_scan1<<<BB, 256>>>();
    k_erodeH<<<dim3(32, BB), 256>>>();
    k_erodeV<<<512, 256>>>();
    k_selBG<<<BB, 512>>>(x);
    k_bgsel<<<dim3(32, BB), 256>>>();
    k_fgsel<<<dim3(8, BB), 256>>>();
    k_finish<<<2 * BB, 512>>>();
    k_out<<<dim3(32, BB), 256>>>(out);
}